// round 2
// baseline (speedup 1.0000x reference)
#include <cuda_runtime.h>
#include <math.h>
#include <stdint.h>
#include <stddef.h>

#define B_ 2048
#define I_ 512
#define H_ 512
#define L_ 32
#define D_ 1024
#define O_ 512

// ---------------- device scratch (no allocs allowed) ----------------
__device__ float g_Wcat_enc[4 * H_ * 2 * H_];   // [2048][1024] = [Wih|Whh]
__device__ float g_Wcat_dec[4 * H_ * 2 * H_];
__device__ float g_bias_enc[4 * H_];            // bih + bhh
__device__ float g_bias_dec[4 * H_];
__device__ float g_t2hT[D_ * H_];               // t2h_W transposed: [D][H]
__device__ float g_inp[B_ * H_];
__device__ float g_hx [B_ * H_];
__device__ float g_cx [B_ * H_];
__device__ float g_hx2[B_ * H_];
__device__ float g_cx2[B_ * H_];
__device__ float g_gates[B_ * 4 * H_];          // 16 MB
__device__ float g_zemb[L_ * B_ * H_];          // 128 MB: decoder inputs

// ---------------- generic NT GEMM: C = A @ W^T + bias ----------------
// A is [M,K] row-major. If A1 != nullptr, A is split: k<512 from A0 (ld 512),
// k>=512 from A1 (ld 512). W is [N,K] row-major. C has leading dim ldC.
#define BM 128
#define BN 128
#define BK 16

__device__ __forceinline__ float4 ld_split(const float* __restrict__ A0,
                                           const float* __restrict__ A1,
                                           int lda, int row, int k) {
    const float* base = A0;
    if (A1 != nullptr && k >= H_) { base = A1; k -= H_; }
    return *reinterpret_cast<const float4*>(base + (size_t)row * lda + k);
}

__global__ __launch_bounds__(256, 2)
void gemm_nt_kernel(const float* __restrict__ A0, const float* __restrict__ A1,
                    const float* __restrict__ W,  const float* __restrict__ bias,
                    float* __restrict__ C, int M, int N, int K, int ldC)
{
    __shared__ float As[2][BK][BM + 4];
    __shared__ float Ws[2][BK][BN + 4];

    const int t    = threadIdx.x;
    const int brow = blockIdx.y * BM;
    const int bcol = blockIdx.x * BN;
    const int lda  = (A1 != nullptr) ? H_ : K;

    // each thread loads 2 float4 of A and 2 of W per tile
    const int r0  = t >> 1;                  // row within tile (0..127)
    const int kq0 = (t & 1) * 2;             // float4 index pair: {0,1} or {2,3}
    const int kq1 = kq0 + 1;

    float4 pa0, pa1, pw0, pw1;

    // prologue: tile 0
    pa0 = ld_split(A0, A1, lda, brow + r0, 0 + kq0 * 4);
    pa1 = ld_split(A0, A1, lda, brow + r0, 0 + kq1 * 4);
    pw0 = *reinterpret_cast<const float4*>(W + (size_t)(bcol + r0) * K + kq0 * 4);
    pw1 = *reinterpret_cast<const float4*>(W + (size_t)(bcol + r0) * K + kq1 * 4);
    {
        As[0][kq0*4+0][r0]=pa0.x; As[0][kq0*4+1][r0]=pa0.y; As[0][kq0*4+2][r0]=pa0.z; As[0][kq0*4+3][r0]=pa0.w;
        As[0][kq1*4+0][r0]=pa1.x; As[0][kq1*4+1][r0]=pa1.y; As[0][kq1*4+2][r0]=pa1.z; As[0][kq1*4+3][r0]=pa1.w;
        Ws[0][kq0*4+0][r0]=pw0.x; Ws[0][kq0*4+1][r0]=pw0.y; Ws[0][kq0*4+2][r0]=pw0.z; Ws[0][kq0*4+3][r0]=pw0.w;
        Ws[0][kq1*4+0][r0]=pw1.x; Ws[0][kq1*4+1][r0]=pw1.y; Ws[0][kq1*4+2][r0]=pw1.z; Ws[0][kq1*4+3][r0]=pw1.w;
    }
    __syncthreads();

    float acc[8][8];
    #pragma unroll
    for (int i = 0; i < 8; i++)
        #pragma unroll
        for (int j = 0; j < 8; j++) acc[i][j] = 0.f;

    const int tx = t & 15, ty = t >> 4;
    const int mo = ty * 8, no = tx * 8;
    const int nk = K / BK;

    for (int kt = 0; kt < nk; kt++) {
        const int cur = kt & 1;
        if (kt + 1 < nk) {
            const int k0 = (kt + 1) * BK;
            pa0 = ld_split(A0, A1, lda, brow + r0, k0 + kq0 * 4);
            pa1 = ld_split(A0, A1, lda, brow + r0, k0 + kq1 * 4);
            pw0 = *reinterpret_cast<const float4*>(W + (size_t)(bcol + r0) * K + k0 + kq0 * 4);
            pw1 = *reinterpret_cast<const float4*>(W + (size_t)(bcol + r0) * K + k0 + kq1 * 4);
        }
        #pragma unroll
        for (int kk = 0; kk < BK; kk++) {
            float a[8], b[8];
            #pragma unroll
            for (int i = 0; i < 8; i++) a[i] = As[cur][kk][mo + i];
            #pragma unroll
            for (int j = 0; j < 8; j++) b[j] = Ws[cur][kk][no + j];
            #pragma unroll
            for (int i = 0; i < 8; i++)
                #pragma unroll
                for (int j = 0; j < 8; j++)
                    acc[i][j] = fmaf(a[i], b[j], acc[i][j]);
        }
        if (kt + 1 < nk) {
            const int nb = cur ^ 1;
            As[nb][kq0*4+0][r0]=pa0.x; As[nb][kq0*4+1][r0]=pa0.y; As[nb][kq0*4+2][r0]=pa0.z; As[nb][kq0*4+3][r0]=pa0.w;
            As[nb][kq1*4+0][r0]=pa1.x; As[nb][kq1*4+1][r0]=pa1.y; As[nb][kq1*4+2][r0]=pa1.z; As[nb][kq1*4+3][r0]=pa1.w;
            Ws[nb][kq0*4+0][r0]=pw0.x; Ws[nb][kq0*4+1][r0]=pw0.y; Ws[nb][kq0*4+2][r0]=pw0.z; Ws[nb][kq0*4+3][r0]=pw0.w;
            Ws[nb][kq1*4+0][r0]=pw1.x; Ws[nb][kq1*4+1][r0]=pw1.y; Ws[nb][kq1*4+2][r0]=pw1.z; Ws[nb][kq1*4+3][r0]=pw1.w;
        }
        __syncthreads();
    }

    #pragma unroll
    for (int i = 0; i < 8; i++) {
        const size_t off = (size_t)(brow + mo + i) * ldC + bcol + no;
        #pragma unroll
        for (int j = 0; j < 8; j++)
            C[off + j] = acc[i][j] + bias[bcol + no + j];
    }
}

// ---------------- pointwise LSTM cell ----------------
__device__ __forceinline__ float sigmoidf_(float x) { return 1.f / (1.f + expf(-x)); }

__global__ void lstm_pointwise(const float* __restrict__ gates,
                               float* __restrict__ hx, float* __restrict__ cx)
{
    const int idx = blockIdx.x * blockDim.x + threadIdx.x;
    if (idx >= B_ * H_) return;
    const int b = idx >> 9, h = idx & (H_ - 1);
    const float* g = gates + (size_t)b * (4 * H_);
    const float ii = sigmoidf_(g[h]);
    const float ff = sigmoidf_(g[h + H_]);
    const float gg = tanhf    (g[h + 2 * H_]);
    const float oo = sigmoidf_(g[h + 3 * H_]);
    const float c  = ff * cx[idx] + ii * gg;
    cx[idx] = c;
    hx[idx] = oo * tanhf(c);
}

// ---------------- softmax + straight-through + gathered inp ----------------
__global__ __launch_bounds__(256)
void softmax_st_kernel(const float* __restrict__ logits_base,  // d_out logits region [B][L][D]
                       const float* __restrict__ gumbel,       // [L][B][D]
                       int t,
                       float* __restrict__ onehot_base,        // d_out one_hot region [B][L][D]
                       float* __restrict__ messages,           // d_out messages [B][L]
                       const float* __restrict__ t2hT,         // [D][H]
                       const float* __restrict__ t2h_b,
                       float* __restrict__ inp,                // [B][H]
                       float* __restrict__ zembt)              // [B][H] slot t
{
    const int b   = blockIdx.x;
    const int tid = threadIdx.x;
    const float* pre = logits_base + (size_t)b * (L_ * D_) + (size_t)t * D_;
    const float* gm  = gumbel + ((size_t)t * B_ + b) * D_;

    float y[4];
    float vmax = -INFINITY; int imax = 0;
    #pragma unroll
    for (int q = 0; q < 4; q++) {
        const int d = tid + q * 256;
        y[q] = pre[d] + gm[d];
        if (y[q] > vmax) { vmax = y[q]; imax = d; }
    }
    __shared__ float sv[256];
    __shared__ int   si[256];
    sv[tid] = vmax; si[tid] = imax;
    __syncthreads();
    for (int s = 128; s > 0; s >>= 1) {
        if (tid < s) {
            const float ov = sv[tid + s]; const int oi = si[tid + s];
            if (ov > sv[tid] || (ov == sv[tid] && oi < si[tid])) { sv[tid] = ov; si[tid] = oi; }
        }
        __syncthreads();
    }
    vmax = sv[0]; imax = si[0];

    float lsum = 0.f;
    #pragma unroll
    for (int q = 0; q < 4; q++) lsum += expf(y[q] - vmax);
    __shared__ float ss[256];
    ss[tid] = lsum;
    __syncthreads();
    for (int s = 128; s > 0; s >>= 1) {
        if (tid < s) ss[tid] += ss[tid + s];
        __syncthreads();
    }
    const float s_amax = 1.f / ss[0];            // soft[amax]
    const float zval   = s_amax + (1.f - s_amax); // straight-through value

    float* oh = onehot_base + (size_t)b * (L_ * D_) + (size_t)t * D_;
    #pragma unroll
    for (int q = 0; q < 4; q++) {
        const int d = tid + q * 256;
        oh[d] = (d == imax) ? zval : 0.f;
    }
    if (tid == 0) messages[(size_t)b * L_ + t] = (float)imax;

    // inp = z @ t2h_W^T + b  ==  zval * t2h_W[:, imax] + t2h_b  (all other z exactly 0)
    const float* wrow = t2hT + (size_t)imax * H_;
    #pragma unroll
    for (int q = 0; q < 2; q++) {
        const int h = tid + q * 256;
        const float p = zval * wrow[h];
        const float v = p + t2h_b[h];
        inp  [(size_t)b * H_ + h] = v;
        zembt[(size_t)b * H_ + h] = v;
    }
}

// ---------------- packing / transpose / zero ----------------
__global__ void pack_lstm_kernel(const float* __restrict__ Wih, const float* __restrict__ Whh,
                                 const float* __restrict__ bih, const float* __restrict__ bhh,
                                 float* __restrict__ Wcat, float* __restrict__ bias)
{
    const int idx = blockIdx.x * 256 + threadIdx.x;
    if (idx < 4 * H_ * 2 * H_) {
        const int r = idx >> 10, k = idx & 1023;
        Wcat[idx] = (k < H_) ? Wih[(size_t)r * H_ + k] : Whh[(size_t)r * H_ + (k - H_)];
    }
    if (idx < 4 * H_) bias[idx] = bih[idx] + bhh[idx];
}

__global__ void transpose_t2h_kernel(const float* __restrict__ W, float* __restrict__ WT)
{
    const int idx = blockIdx.x * 256 + threadIdx.x;   // over D*H
    if (idx >= D_ * H_) return;
    const int d = idx / H_, h = idx - d * H_;
    WT[idx] = W[(size_t)h * D_ + d];
}

__global__ void zero_kernel(float* __restrict__ p, int n)
{
    const int idx = blockIdx.x * 256 + threadIdx.x;
    if (idx < n) p[idx] = 0.f;
}

// ---------------- host ----------------
extern "C" void kernel_launch(void* const* d_in, const int* in_sizes, int n_in,
                              void* d_out, int out_size)
{
    const float* x       = (const float*)d_in[0];
    const float* gumbel  = (const float*)d_in[1];
    const float* in_W    = (const float*)d_in[2];
    const float* in_b    = (const float*)d_in[3];
    const float* out_W   = (const float*)d_in[4];
    const float* out_b   = (const float*)d_in[5];
    const float* enc_Wih = (const float*)d_in[6];
    const float* enc_Whh = (const float*)d_in[7];
    const float* enc_bih = (const float*)d_in[8];
    const float* enc_bhh = (const float*)d_in[9];
    const float* dec_Wih = (const float*)d_in[10];
    const float* dec_Whh = (const float*)d_in[11];
    const float* dec_bih = (const float*)d_in[12];
    const float* dec_bhh = (const float*)d_in[13];
    const float* h2t_W   = (const float*)d_in[14];
    const float* h2t_b   = (const float*)d_in[15];
    const float* t2h_W   = (const float*)d_in[16];
    const float* t2h_b   = (const float*)d_in[17];

    float* out        = (float*)d_out;
    float* out_recon  = out;
    float* out_onehot = out + (size_t)B_ * O_;
    float* out_logits = out_onehot + (size_t)B_ * L_ * D_;
    float* out_msg    = out_logits + (size_t)B_ * L_ * D_;

    float *Wce, *Wcd, *be, *bd, *t2hT, *inp, *hx, *cx, *hx2, *cx2, *gates, *zemb;
    cudaGetSymbolAddress((void**)&Wce,   g_Wcat_enc);
    cudaGetSymbolAddress((void**)&Wcd,   g_Wcat_dec);
    cudaGetSymbolAddress((void**)&be,    g_bias_enc);
    cudaGetSymbolAddress((void**)&bd,    g_bias_dec);
    cudaGetSymbolAddress((void**)&t2hT,  g_t2hT);
    cudaGetSymbolAddress((void**)&inp,   g_inp);
    cudaGetSymbolAddress((void**)&hx,    g_hx);
    cudaGetSymbolAddress((void**)&cx,    g_cx);
    cudaGetSymbolAddress((void**)&hx2,   g_hx2);
    cudaGetSymbolAddress((void**)&cx2,   g_cx2);
    cudaGetSymbolAddress((void**)&gates, g_gates);
    cudaGetSymbolAddress((void**)&zemb,  g_zemb);

    // weight prep
    pack_lstm_kernel<<<(4 * H_ * 2 * H_ + 255) / 256, 256>>>(enc_Wih, enc_Whh, enc_bih, enc_bhh, Wce, be);
    pack_lstm_kernel<<<(4 * H_ * 2 * H_ + 255) / 256, 256>>>(dec_Wih, dec_Whh, dec_bih, dec_bhh, Wcd, bd);
    transpose_t2h_kernel<<<(D_ * H_ + 255) / 256, 256>>>(t2h_W, t2hT);

    // init states: hx=0, inp=0, cx = x @ in_W^T + in_b  ;  decoder hx2=cx2=0
    zero_kernel<<<(B_ * H_ + 255) / 256, 256>>>(inp, B_ * H_);
    zero_kernel<<<(B_ * H_ + 255) / 256, 256>>>(hx,  B_ * H_);
    zero_kernel<<<(B_ * H_ + 255) / 256, 256>>>(hx2, B_ * H_);
    zero_kernel<<<(B_ * H_ + 255) / 256, 256>>>(cx2, B_ * H_);
    gemm_nt_kernel<<<dim3(H_ / BN, B_ / BM), 256>>>(x, nullptr, in_W, in_b, cx, B_, H_, I_, H_);

    // ---- encoder ----
    for (int t = 0; t < L_; t++) {
        gemm_nt_kernel<<<dim3((4 * H_) / BN, B_ / BM), 256>>>(inp, hx, Wce, be, gates, B_, 4 * H_, 2 * H_, 4 * H_);
        lstm_pointwise<<<(B_ * H_) / 256, 256>>>(gates, hx, cx);
        gemm_nt_kernel<<<dim3(D_ / BN, B_ / BM), 256>>>(hx, nullptr, h2t_W, h2t_b,
                                                        out_logits + (size_t)t * D_, B_, D_, H_, L_ * D_);
        softmax_st_kernel<<<B_, 256>>>(out_logits, gumbel, t, out_onehot, out_msg,
                                       t2hT, t2h_b, inp, zemb + (size_t)t * B_ * H_);
    }

    // ---- decoder ----
    for (int t = 0; t < L_; t++) {
        gemm_nt_kernel<<<dim3((4 * H_) / BN, B_ / BM), 256>>>(zemb + (size_t)t * B_ * H_, hx2, Wcd, bd,
                                                              gates, B_, 4 * H_, 2 * H_, 4 * H_);
        lstm_pointwise<<<(B_ * H_) / 256, 256>>>(gates, hx2, cx2);
    }
    gemm_nt_kernel<<<dim3(O_ / BN, B_ / BM), 256>>>(hx2, nullptr, out_W, out_b, out_recon, B_, O_, H_, O_);
}

// round 4
// speedup vs baseline: 2.6928x; 2.6928x over previous
#include <cuda_runtime.h>
#include <cuda_fp16.h>
#include <math.h>
#include <stdint.h>
#include <stddef.h>

#define B_ 2048
#define H_ 512
#define L_ 32
#define D_ 1024
#define O_ 512

// ---------------- device scratch ----------------
__device__ float g_be[2048];
__device__ float g_bd[2048];
__device__ float g_t2hT[D_ * H_];
__device__ float g_cx[B_ * H_];
__device__ float g_cx2[B_ * H_];
__device__ float g_gates[B_ * 2048];
__device__ __half g_We1[2048 * 1024], g_We2[2048 * 1024];
__device__ __half g_Wd1[2048 * 1024];
__device__ __half g_h2t1[D_ * H_], g_h2t2[D_ * H_];
__device__ __half g_inW1[H_ * 512], g_inW2[H_ * 512];
__device__ __half g_outW1[O_ * H_];
__device__ __half g_x1[B_ * 512], g_x2[B_ * 512];
__device__ __half g_inp1[B_ * H_], g_inp2[B_ * H_];
__device__ __half g_hxA[B_ * H_], g_hxB[B_ * H_];
__device__ __half g_hx21[B_ * H_];
__device__ __half g_z1[L_ * B_ * H_];

// ---------------- PTX helpers (baseline ISA only) ----------------
__device__ __forceinline__ uint32_t smem_u32(const void* p) {
    uint32_t a;
    asm("{ .reg .u64 t; cvta.to.shared.u64 t, %1; cvt.u32.u64 %0, t; }" : "=r"(a) : "l"(p));
    return a;
}
__device__ __forceinline__ void cpa16(uint32_t sa, const void* g) {
    asm volatile("cp.async.cg.shared.global [%0], [%1], 16;" :: "r"(sa), "l"(g));
}
__device__ __forceinline__ void ldsm4(uint32_t* r, uint32_t addr) {
    asm volatile("ldmatrix.sync.aligned.m8n8.x4.shared.b16 {%0,%1,%2,%3}, [%4];"
        : "=r"(r[0]), "=r"(r[1]), "=r"(r[2]), "=r"(r[3]) : "r"(addr));
}
__device__ __forceinline__ void mma16816(float* c, const uint32_t* a, uint32_t b0, uint32_t b1) {
    asm volatile("mma.sync.aligned.m16n8k16.row.col.f32.f16.f16.f32 "
        "{%0,%1,%2,%3}, {%4,%5,%6,%7}, {%8,%9}, {%0,%1,%2,%3};"
        : "+f"(c[0]), "+f"(c[1]), "+f"(c[2]), "+f"(c[3])
        : "r"(a[0]), "r"(a[1]), "r"(a[2]), "r"(a[3]), "r"(b0), "r"(b1));
}

// ---------------- split-fp16 mma.sync GEMM ----------------
// C[M,N] = sum_pairs A_pa @ B_pb^T + bias.
// NS=2: pairs (0,0),(0,1),(1,0)  [3xfp16 ~ fp32 accuracy]; NS=1: pair (0,0).
// A split arrays [M][512], K spans two halves: chunks < nck0 from a0*, else a1*.
// B split arrays [N][ldb]. Tile 128x128, K-chunk 32, 2-stage cp.async pipeline.
template <int NS>
__global__ __launch_bounds__(256, 2)
void gemm_sp(const __half* a00, const __half* a01,
             const __half* a10, const __half* a11,
             const __half* b0, const __half* b1,
             const float* __restrict__ bias, float* __restrict__ C,
             int ldb, int ldC, int nck0, int nck)
{
    extern __shared__ char dsm[];
    const uint32_t sb0 = smem_u32(dsm);
    const int tid = threadIdx.x;
    const int lane = tid & 31, warp = tid >> 5;
    const int wm = warp >> 2, wn = warp & 3;            // 2 x 4 warps
    const int brow = blockIdx.y * 128, bcol = blockIdx.x * 128;
    constexpr uint32_t TB = 10240u;                     // 128 rows x 40 halves
    constexpr uint32_t STB = 2 * NS * TB;

    const __half* A0[2] = {a00, a01};
    const __half* A1[2] = {a10, a11};
    const __half* Bs[2] = {b0, b1};

    auto load_stage = [&](int s, int kc) {
        const uint32_t st = sb0 + (uint32_t)s * STB;
        const __half* const* ap = (kc < nck0) ? A0 : A1;
        const int kcl = (kc < nck0) ? kc : kc - nck0;
        #pragma unroll
        for (int t = 0; t < NS; t++) {
            const __half* ga = ap[t] + (size_t)brow * 512 + kcl * 32;
            const __half* gb = Bs[t] + (size_t)bcol * ldb + kc * 32;
            #pragma unroll
            for (int r = 0; r < 2; r++) {
                const int lin = r * 256 + tid;
                const int c16 = lin >> 7, row = lin & 127;
                cpa16(st + t * TB + row * 80 + c16 * 16, ga + (size_t)row * 512 + c16 * 8);
                cpa16(st + (NS + t) * TB + row * 80 + c16 * 16, gb + (size_t)row * ldb + c16 * 8);
            }
        }
        asm volatile("cp.async.commit_group;" ::: "memory");
    };

    float acc[4][4][4];
    #pragma unroll
    for (int i = 0; i < 4; i++)
        #pragma unroll
        for (int j = 0; j < 4; j++)
            #pragma unroll
            for (int q = 0; q < 4; q++) acc[i][j][q] = 0.f;

    load_stage(0, 0);
    load_stage(1, 1);

    const int pa[3] = {0, 0, 1}, pb[3] = {0, 1, 0};
    constexpr int NP = (NS == 2) ? 3 : 1;

    for (int c = 0; c < nck; c++) {
        const int s = c & 1;
        if (c == nck - 1) asm volatile("cp.async.wait_group 0;" ::: "memory");
        else              asm volatile("cp.async.wait_group 1;" ::: "memory");
        __syncthreads();
        const uint32_t st = sb0 + (uint32_t)s * STB;
        #pragma unroll
        for (int p = 0; p < NP; p++) {
            const uint32_t at = st + pa[p] * TB;
            const uint32_t bt = st + (NS + pb[p]) * TB;
            #pragma unroll
            for (int ks = 0; ks < 2; ks++) {
                uint32_t aF[4][4], bF[2][4];
                #pragma unroll
                for (int i = 0; i < 4; i++) {
                    const int row = wm * 64 + i * 16 + (lane & 15);
                    ldsm4(aF[i], at + row * 80 + (ks * 16 + (lane >> 4) * 8) * 2);
                }
                #pragma unroll
                for (int jp = 0; jp < 2; jp++) {
                    const int rn = wn * 32 + jp * 16 + (lane & 7) + ((lane >> 4) << 3);
                    ldsm4(bF[jp], bt + rn * 80 + (ks * 16 + ((lane >> 3) & 1) * 8) * 2);
                }
                #pragma unroll
                for (int i = 0; i < 4; i++)
                    #pragma unroll
                    for (int j = 0; j < 4; j++)
                        mma16816(acc[i][j], aF[i], bF[j >> 1][(j & 1) * 2], bF[j >> 1][(j & 1) * 2 + 1]);
            }
        }
        __syncthreads();
        if (c + 2 < nck) load_stage(s, c + 2);
    }

    const int er = lane >> 2, ec = (lane & 3) * 2;
    #pragma unroll
    for (int i = 0; i < 4; i++) {
        const int row = brow + wm * 64 + i * 16 + er;
        #pragma unroll
        for (int j = 0; j < 4; j++) {
            const int col = bcol + wn * 32 + j * 8 + ec;
            const float bz0 = bias[col], bz1 = bias[col + 1];
            float* c0 = C + (size_t)row * ldC + col;
            float* c1 = C + (size_t)(row + 8) * ldC + col;
            c0[0] = acc[i][j][0] + bz0; c0[1] = acc[i][j][1] + bz1;
            c1[0] = acc[i][j][2] + bz0; c1[1] = acc[i][j][3] + bz1;
        }
    }
}

// ---------------- pointwise ----------------
__device__ __forceinline__ float sigf(float x) { return 1.f / (1.f + expf(-x)); }
__device__ __forceinline__ void split2h(float v, __half* p1, __half* p2, size_t i) {
    __half h1 = __float2half_rn(v);
    p1[i] = h1; p2[i] = __float2half_rn(v - __half2float(h1));
}

__global__ void lstm_pw2s(const float* __restrict__ g, float* __restrict__ cx,
                          __half* h1, __half* h2)
{
    const int i = blockIdx.x * 256 + threadIdx.x;
    const int b = i >> 9, h = i & 511;
    const float* gr = g + (size_t)b * 2048;
    const float c = sigf(gr[h + 512]) * cx[i] + sigf(gr[h]) * tanhf(gr[h + 1024]);
    cx[i] = c;
    split2h(sigf(gr[h + 1536]) * tanhf(c), h1, h2, i);
}
__global__ void lstm_pw1s(const float* __restrict__ g, float* __restrict__ cx, __half* h1)
{
    const int i = blockIdx.x * 256 + threadIdx.x;
    const int b = i >> 9, h = i & 511;
    const float* gr = g + (size_t)b * 2048;
    const float c = sigf(gr[h + 512]) * cx[i] + sigf(gr[h]) * tanhf(gr[h + 1024]);
    cx[i] = c;
    h1[i] = __float2half_rn(sigf(gr[h + 1536]) * tanhf(c));
}

__global__ __launch_bounds__(256)
void softmax_st(const float* __restrict__ logits, const float* __restrict__ gumbel, int t,
                float* __restrict__ onehot, float* __restrict__ messages,
                const float* __restrict__ t2hT, const float* __restrict__ t2h_b,
                __half* i1, __half* i2, __half* z1)
{
    const int b = blockIdx.x, tid = threadIdx.x;
    const float* pre = logits + (size_t)b * (L_ * D_) + (size_t)t * D_;
    const float* gm = gumbel + ((size_t)t * B_ + b) * D_;
    float y[4]; float vmax = -INFINITY; int imax = 0;
    #pragma unroll
    for (int q = 0; q < 4; q++) {
        const int d = tid + q * 256;
        y[q] = pre[d] + gm[d];
        if (y[q] > vmax) { vmax = y[q]; imax = d; }
    }
    __shared__ float sv[256]; __shared__ int si[256]; __shared__ float ss[256];
    sv[tid] = vmax; si[tid] = imax;
    __syncthreads();
    for (int s = 128; s > 0; s >>= 1) {
        if (tid < s) {
            const float ov = sv[tid + s]; const int oi = si[tid + s];
            if (ov > sv[tid] || (ov == sv[tid] && oi < si[tid])) { sv[tid] = ov; si[tid] = oi; }
        }
        __syncthreads();
    }
    vmax = sv[0]; imax = si[0];
    float ls = 0.f;
    #pragma unroll
    for (int q = 0; q < 4; q++) ls += expf(y[q] - vmax);
    ss[tid] = ls;
    __syncthreads();
    for (int s = 128; s > 0; s >>= 1) { if (tid < s) ss[tid] += ss[tid + s]; __syncthreads(); }
    const float sm = 1.f / ss[0];
    const float zval = sm + (1.f - sm);
    float* oh = onehot + (size_t)b * (L_ * D_) + (size_t)t * D_;
    #pragma unroll
    for (int q = 0; q < 4; q++) { const int d = tid + q * 256; oh[d] = (d == imax) ? zval : 0.f; }
    if (tid == 0) messages[(size_t)b * L_ + t] = (float)imax;
    const float* wrow = t2hT + (size_t)imax * H_;
    const size_t zo = ((size_t)t * B_ + b) * H_;
    #pragma unroll
    for (int q = 0; q < 2; q++) {
        const int h = tid + q * 256;
        const float v = zval * wrow[h] + t2h_b[h];
        __half h1 = __float2half_rn(v);
        i1[(size_t)b * H_ + h] = h1;
        i2[(size_t)b * H_ + h] = __float2half_rn(v - __half2float(h1));
        z1[zo + h] = h1;
    }
}

// ---------------- prep ----------------
__global__ void pack_split2(const float* Wih, const float* Whh, const float* bih,
                            const float* bhh, __half* w1, __half* w2, float* bias)
{
    const int i = blockIdx.x * 256 + threadIdx.x;
    if (i < 2048 * 1024) {
        const int r = i >> 10, k = i & 1023;
        const float v = (k < 512) ? Wih[(size_t)r * 512 + k] : Whh[(size_t)r * 512 + (k - 512)];
        split2h(v, w1, w2, i);
    }
    if (i < 2048) bias[i] = bih[i] + bhh[i];
}
__global__ void pack_conv1(const float* Wih, const float* Whh, const float* bih,
                           const float* bhh, __half* w1, float* bias)
{
    const int i = blockIdx.x * 256 + threadIdx.x;
    if (i < 2048 * 1024) {
        const int r = i >> 10, k = i & 1023;
        const float v = (k < 512) ? Wih[(size_t)r * 512 + k] : Whh[(size_t)r * 512 + (k - 512)];
        w1[i] = __float2half_rn(v);
    }
    if (i < 2048) bias[i] = bih[i] + bhh[i];
}
__global__ void split2_arr(const float* s, __half* t1, __half* t2, int n)
{ const int i = blockIdx.x * 256 + threadIdx.x; if (i < n) split2h(s[i], t1, t2, i); }
__global__ void conv1_arr(const float* s, __half* t1, int n)
{ const int i = blockIdx.x * 256 + threadIdx.x; if (i < n) t1[i] = __float2half_rn(s[i]); }
__global__ void transpose_t2h(const float* W, float* WT)
{
    const int i = blockIdx.x * 256 + threadIdx.x;
    if (i >= D_ * H_) return;
    const int d = i / H_, h = i - d * H_;
    WT[i] = W[(size_t)h * D_ + d];
}
__global__ void zero_state(__half* i1, __half* i2, __half* h1, __half* h2,
                           __half* q1, float* c2)
{
    const int i = blockIdx.x * 256 + threadIdx.x;
    if (i >= B_ * H_) return;
    const __half z = __float2half_rn(0.f);
    i1[i] = z; i2[i] = z; h1[i] = z; h2[i] = z; q1[i] = z; c2[i] = 0.f;
}

// ---------------- host ----------------
#define SYM(p, s) cudaGetSymbolAddress((void**)&p, s)

extern "C" void kernel_launch(void* const* d_in, const int* in_sizes, int n_in,
                              void* d_out, int out_size)
{
    const float* x = (const float*)d_in[0];
    const float* gumbel = (const float*)d_in[1];
    const float* in_W = (const float*)d_in[2];
    const float* in_b = (const float*)d_in[3];
    const float* out_W = (const float*)d_in[4];
    const float* out_b = (const float*)d_in[5];
    const float* eWih = (const float*)d_in[6];
    const float* eWhh = (const float*)d_in[7];
    const float* ebih = (const float*)d_in[8];
    const float* ebhh = (const float*)d_in[9];
    const float* dWih = (const float*)d_in[10];
    const float* dWhh = (const float*)d_in[11];
    const float* dbih = (const float*)d_in[12];
    const float* dbhh = (const float*)d_in[13];
    const float* h2t_b = (const float*)d_in[15];
    const float* h2t_W = (const float*)d_in[14];
    const float* t2h_W = (const float*)d_in[16];
    const float* t2h_b = (const float*)d_in[17];

    float* out = (float*)d_out;
    float* o_recon = out;
    float* o_oh = out + (size_t)B_ * O_;
    float* o_lg = o_oh + (size_t)B_ * L_ * D_;
    float* o_msg = o_lg + (size_t)B_ * L_ * D_;

    float *be, *bd, *t2hT, *cx, *cx2, *gates;
    __half *We1, *We2, *Wd1, *h2t1, *h2t2, *inW1, *inW2, *outW1;
    __half *x1, *x2, *inp1, *inp2, *hxA, *hxB, *hx21, *z1;
    SYM(be, g_be); SYM(bd, g_bd); SYM(t2hT, g_t2hT); SYM(cx, g_cx);
    SYM(cx2, g_cx2); SYM(gates, g_gates);
    SYM(We1, g_We1); SYM(We2, g_We2); SYM(Wd1, g_Wd1);
    SYM(h2t1, g_h2t1); SYM(h2t2, g_h2t2);
    SYM(inW1, g_inW1); SYM(inW2, g_inW2); SYM(outW1, g_outW1);
    SYM(x1, g_x1); SYM(x2, g_x2); SYM(inp1, g_inp1); SYM(inp2, g_inp2);
    SYM(hxA, g_hxA); SYM(hxB, g_hxB); SYM(hx21, g_hx21); SYM(z1, g_z1);

    const int S2 = 2 * 2 * 2 * 10240;   // NS=2: 81920
    const int S1 = 2 * 1 * 2 * 10240;   // NS=1: 40960
    cudaFuncSetAttribute(gemm_sp<2>, cudaFuncAttributeMaxDynamicSharedMemorySize, S2);
    cudaFuncSetAttribute(gemm_sp<1>, cudaFuncAttributeMaxDynamicSharedMemorySize, S1);

    // prep
    pack_split2<<<8192, 256>>>(eWih, eWhh, ebih, ebhh, We1, We2, be);
    pack_conv1<<<8192, 256>>>(dWih, dWhh, dbih, dbhh, Wd1, bd);
    transpose_t2h<<<(D_ * H_ + 255) / 256, 256>>>(t2h_W, t2hT);
    split2_arr<<<2048, 256>>>(h2t_W, h2t1, h2t2, D_ * H_);
    split2_arr<<<1024, 256>>>(in_W, inW1, inW2, H_ * 512);
    conv1_arr<<<1024, 256>>>(out_W, outW1, O_ * H_);
    split2_arr<<<4096, 256>>>(x, x1, x2, B_ * 512);
    zero_state<<<4096, 256>>>(inp1, inp2, hxA, hxB, hx21, cx2);

    // cx = x @ in_W^T + in_b  (3-pair fp16)
    gemm_sp<2><<<dim3(4, 16), 256, S2>>>(x1, x2, x1, x2, inW1, inW2, in_b, cx,
                                         512, 512, 16, 16);

    // ---- encoder ----
    for (int t = 0; t < L_; t++) {
        gemm_sp<2><<<dim3(16, 16), 256, S2>>>(inp1, inp2, hxA, hxB, We1, We2, be,
                                              gates, 1024, 2048, 16, 32);
        lstm_pw2s<<<4096, 256>>>(gates, cx, hxA, hxB);
        gemm_sp<2><<<dim3(8, 16), 256, S2>>>(hxA, hxB, hxA, hxB, h2t1, h2t2, h2t_b,
                                             o_lg + (size_t)t * D_, 512, L_ * D_, 16, 16);
        softmax_st<<<B_, 256>>>(o_lg, gumbel, t, o_oh, o_msg, t2hT, t2h_b,
                                inp1, inp2, z1);
    }

    // ---- decoder ----
    for (int t = 0; t < L_; t++) {
        gemm_sp<1><<<dim3(16, 16), 256, S1>>>(z1 + (size_t)t * B_ * H_, nullptr,
                                              hx21, nullptr, Wd1, nullptr, bd,
                                              gates, 1024, 2048, 16, 32);
        lstm_pw1s<<<4096, 256>>>(gates, cx2, hx21);
    }
    gemm_sp<1><<<dim3(4, 16), 256, S1>>>(hx21, nullptr, hx21, nullptr, outW1, nullptr,
                                         out_b, o_recon, 512, 512, 16, 16);
}

// round 5
// speedup vs baseline: 2.8451x; 1.0566x over previous
#include <cuda_runtime.h>
#include <cuda_fp16.h>
#include <math.h>
#include <stdint.h>
#include <stddef.h>

#define B_ 2048
#define H_ 512
#define L_ 32
#define D_ 1024
#define O_ 512

// ---------------- device scratch ----------------
__device__ float g_be[2048];
__device__ float g_bd[2048];
__device__ float g_t2hT[D_ * H_];
__device__ float g_cx[B_ * H_];
__device__ float g_cx2[B_ * H_];
__device__ float g_gates[B_ * 2048];
__device__ __half g_We1[2048 * 1024], g_We2[2048 * 1024];
__device__ __half g_Wd1[2048 * 1024];
__device__ __half g_h2t1[D_ * H_], g_h2t2[D_ * H_];
__device__ __half g_inW1[H_ * 512], g_inW2[H_ * 512];
__device__ __half g_outW1[O_ * H_];
__device__ __half g_x1[B_ * 512], g_x2[B_ * 512];
__device__ __half g_inp1[B_ * H_], g_inp2[B_ * H_];
__device__ __half g_hxA[B_ * H_], g_hxB[B_ * H_];
__device__ __half g_hx21[B_ * H_];
__device__ __half g_z1[L_ * B_ * H_];

// ---------------- PTX helpers (baseline ISA only) ----------------
__device__ __forceinline__ uint32_t smem_u32(const void* p) {
    uint32_t a;
    asm("{ .reg .u64 t; cvta.to.shared.u64 t, %1; cvt.u32.u64 %0, t; }" : "=r"(a) : "l"(p));
    return a;
}
__device__ __forceinline__ void cpa16(uint32_t sa, const void* g) {
    asm volatile("cp.async.cg.shared.global [%0], [%1], 16;" :: "r"(sa), "l"(g));
}
__device__ __forceinline__ void ldsm4(uint32_t* r, uint32_t addr) {
    asm volatile("ldmatrix.sync.aligned.m8n8.x4.shared.b16 {%0,%1,%2,%3}, [%4];"
        : "=r"(r[0]), "=r"(r[1]), "=r"(r[2]), "=r"(r[3]) : "r"(addr));
}
__device__ __forceinline__ void mma16816(float* c, const uint32_t* a, uint32_t b0, uint32_t b1) {
    asm volatile("mma.sync.aligned.m16n8k16.row.col.f32.f16.f16.f32 "
        "{%0,%1,%2,%3}, {%4,%5,%6,%7}, {%8,%9}, {%0,%1,%2,%3};"
        : "+f"(c[0]), "+f"(c[1]), "+f"(c[2]), "+f"(c[3])
        : "r"(a[0]), "r"(a[1]), "r"(a[2]), "r"(a[3]), "r"(b0), "r"(b1));
}

// ---------------- split-fp16 mma.sync GEMM, tile 256x128 ----------------
// C[M,N] = sum over all NS*NS split pairs of A_i @ B_j^T + bias  (exact for NS=2).
// A split arrays [M][512]; K spans two halves: chunks < nck0 from a0*, else a1*.
// B split arrays [N][ldb]. K-chunk 32, 2-stage cp.async pipeline.
// 8 warps: wm = warp>>1 (4 x 64 rows), wn = warp&1 (2 x 64 cols).
template <int NS>
__global__ __launch_bounds__(256, 1)
void gemm_sp(const __half* a00, const __half* a01,
             const __half* a10, const __half* a11,
             const __half* b0, const __half* b1,
             const float* __restrict__ bias, float* __restrict__ C,
             int ldb, int ldC, int nck0, int nck)
{
    extern __shared__ char dsm[];
    const uint32_t sb0 = smem_u32(dsm);
    const int tid = threadIdx.x;
    const int lane = tid & 31, warp = tid >> 5;
    const int wm = warp >> 1, wn = warp & 1;
    const int brow = blockIdx.y * 256, bcol = blockIdx.x * 128;
    constexpr uint32_t TBA = 20480u;            // 256 rows x 40 halves x 2B
    constexpr uint32_t TBB = 10240u;            // 128 rows x 40 halves x 2B
    constexpr uint32_t STB = NS * (TBA + TBB);

    const __half* Aa[2] = {a00, a01};
    const __half* Ab[2] = {a10, a11};
    const __half* Bs[2] = {b0, b1};

    auto load_stage = [&](int s, int kc) {
        const uint32_t st = sb0 + (uint32_t)s * STB;
        const __half* const* ap = (kc < nck0) ? Aa : Ab;
        const int kcl = (kc < nck0) ? kc : kc - nck0;
        #pragma unroll
        for (int t = 0; t < NS; t++) {
            const __half* ga = ap[t] + (size_t)brow * 512 + kcl * 32;
            #pragma unroll
            for (int r = 0; r < 4; r++) {
                const int lin = r * 256 + tid;
                const int row = lin >> 2, c16 = lin & 3;
                cpa16(st + t * TBA + row * 80 + c16 * 16, ga + (size_t)row * 512 + c16 * 8);
            }
            const __half* gb = Bs[t] + (size_t)bcol * ldb + kc * 32;
            #pragma unroll
            for (int r = 0; r < 2; r++) {
                const int lin = r * 256 + tid;
                const int row = lin >> 2, c16 = lin & 3;
                cpa16(st + NS * TBA + t * TBB + row * 80 + c16 * 16, gb + (size_t)row * ldb + c16 * 8);
            }
        }
        asm volatile("cp.async.commit_group;" ::: "memory");
    };

    float acc[4][8][4];
    #pragma unroll
    for (int i = 0; i < 4; i++)
        #pragma unroll
        for (int j = 0; j < 8; j++)
            #pragma unroll
            for (int q = 0; q < 4; q++) acc[i][j][q] = 0.f;

    load_stage(0, 0);
    load_stage(1, 1);

    for (int c = 0; c < nck; c++) {
        const int s = c & 1;
        if (c == nck - 1) asm volatile("cp.async.wait_group 0;" ::: "memory");
        else              asm volatile("cp.async.wait_group 1;" ::: "memory");
        __syncthreads();
        const uint32_t at0 = sb0 + (uint32_t)s * STB;
        const uint32_t bt0 = at0 + NS * TBA;
        #pragma unroll
        for (int ks = 0; ks < 2; ks++) {
            // A fragments for all splits (held in registers, reused across pairs)
            uint32_t aF[NS][4][4];
            #pragma unroll
            for (int t = 0; t < NS; t++)
                #pragma unroll
                for (int i = 0; i < 4; i++) {
                    const int row = wm * 64 + i * 16 + (lane & 15);
                    ldsm4(aF[t][i], at0 + t * TBA + row * 80 + (ks * 16 + (lane >> 4) * 8) * 2);
                }
            // loop over B splits; one bF resident at a time
            #pragma unroll
            for (int tb = 0; tb < NS; tb++) {
                uint32_t bF[4][4];
                #pragma unroll
                for (int jp = 0; jp < 4; jp++) {
                    const int rn = wn * 64 + jp * 16 + (lane & 7) + ((lane >> 4) << 3);
                    ldsm4(bF[jp], bt0 + tb * TBB + rn * 80 + (ks * 16 + ((lane >> 3) & 1) * 8) * 2);
                }
                #pragma unroll
                for (int ta = 0; ta < NS; ta++)
                    #pragma unroll
                    for (int i = 0; i < 4; i++)
                        #pragma unroll
                        for (int j = 0; j < 8; j++)
                            mma16816(acc[i][j], aF[ta][i],
                                     bF[j >> 1][(j & 1) * 2], bF[j >> 1][(j & 1) * 2 + 1]);
            }
        }
        __syncthreads();
        if (c + 2 < nck) load_stage(s, c + 2);
    }

    const int er = lane >> 2, ec = (lane & 3) * 2;
    #pragma unroll
    for (int i = 0; i < 4; i++) {
        const int row = brow + wm * 64 + i * 16 + er;
        #pragma unroll
        for (int j = 0; j < 8; j++) {
            const int col = bcol + wn * 64 + j * 8 + ec;
            const float bz0 = bias[col], bz1 = bias[col + 1];
            float* c0 = C + (size_t)row * ldC + col;
            float* c1 = C + (size_t)(row + 8) * ldC + col;
            c0[0] = acc[i][j][0] + bz0; c0[1] = acc[i][j][1] + bz1;
            c1[0] = acc[i][j][2] + bz0; c1[1] = acc[i][j][3] + bz1;
        }
    }
}

// ---------------- pointwise ----------------
__device__ __forceinline__ float sigf(float x) { return 1.f / (1.f + expf(-x)); }
__device__ __forceinline__ void split2h(float v, __half* p1, __half* p2, size_t i) {
    __half h1 = __float2half_rn(v);
    p1[i] = h1; p2[i] = __float2half_rn(v - __half2float(h1));
}

__global__ void lstm_pw2s(const float* __restrict__ g, float* __restrict__ cx,
                          __half* h1, __half* h2)
{
    const int i = blockIdx.x * 256 + threadIdx.x;
    const int b = i >> 9, h = i & 511;
    const float* gr = g + (size_t)b * 2048;
    const float c = sigf(gr[h + 512]) * cx[i] + sigf(gr[h]) * tanhf(gr[h + 1024]);
    cx[i] = c;
    split2h(sigf(gr[h + 1536]) * tanhf(c), h1, h2, i);
}
__global__ void lstm_pw1s(const float* __restrict__ g, float* __restrict__ cx, __half* h1)
{
    const int i = blockIdx.x * 256 + threadIdx.x;
    const int b = i >> 9, h = i & 511;
    const float* gr = g + (size_t)b * 2048;
    const float c = sigf(gr[h + 512]) * cx[i] + sigf(gr[h]) * tanhf(gr[h + 1024]);
    cx[i] = c;
    h1[i] = __float2half_rn(sigf(gr[h + 1536]) * tanhf(c));
}

__global__ __launch_bounds__(256)
void softmax_st(const float* __restrict__ logits, const float* __restrict__ gumbel, int t,
                float* __restrict__ onehot, float* __restrict__ messages,
                const float* __restrict__ t2hT, const float* __restrict__ t2h_b,
                __half* i1, __half* i2, __half* z1)
{
    const int b = blockIdx.x, tid = threadIdx.x;
    const float* pre = logits + (size_t)b * (L_ * D_) + (size_t)t * D_;
    const float* gm = gumbel + ((size_t)t * B_ + b) * D_;
    float y[4]; float vmax = -INFINITY; int imax = 0;
    #pragma unroll
    for (int q = 0; q < 4; q++) {
        const int d = tid + q * 256;
        y[q] = pre[d] + gm[d];
        if (y[q] > vmax) { vmax = y[q]; imax = d; }
    }
    __shared__ float sv[256]; __shared__ int si[256]; __shared__ float ss[256];
    sv[tid] = vmax; si[tid] = imax;
    __syncthreads();
    for (int s = 128; s > 0; s >>= 1) {
        if (tid < s) {
            const float ov = sv[tid + s]; const int oi = si[tid + s];
            if (ov > sv[tid] || (ov == sv[tid] && oi < si[tid])) { sv[tid] = ov; si[tid] = oi; }
        }
        __syncthreads();
    }
    vmax = sv[0]; imax = si[0];
    float ls = 0.f;
    #pragma unroll
    for (int q = 0; q < 4; q++) ls += expf(y[q] - vmax);
    ss[tid] = ls;
    __syncthreads();
    for (int s = 128; s > 0; s >>= 1) { if (tid < s) ss[tid] += ss[tid + s]; __syncthreads(); }
    const float sm = 1.f / ss[0];
    const float zval = sm + (1.f - sm);
    float* oh = onehot + (size_t)b * (L_ * D_) + (size_t)t * D_;
    #pragma unroll
    for (int q = 0; q < 4; q++) { const int d = tid + q * 256; oh[d] = (d == imax) ? zval : 0.f; }
    if (tid == 0) messages[(size_t)b * L_ + t] = (float)imax;
    const float* wrow = t2hT + (size_t)imax * H_;
    const size_t zo = ((size_t)t * B_ + b) * H_;
    #pragma unroll
    for (int q = 0; q < 2; q++) {
        const int h = tid + q * 256;
        const float v = zval * wrow[h] + t2h_b[h];
        __half h1 = __float2half_rn(v);
        i1[(size_t)b * H_ + h] = h1;
        i2[(size_t)b * H_ + h] = __float2half_rn(v - __half2float(h1));
        z1[zo + h] = h1;
    }
}

// ---------------- prep ----------------
__global__ void pack_split2(const float* Wih, const float* Whh, const float* bih,
                            const float* bhh, __half* w1, __half* w2, float* bias)
{
    const int i = blockIdx.x * 256 + threadIdx.x;
    if (i < 2048 * 1024) {
        const int r = i >> 10, k = i & 1023;
        const float v = (k < 512) ? Wih[(size_t)r * 512 + k] : Whh[(size_t)r * 512 + (k - 512)];
        split2h(v, w1, w2, i);
    }
    if (i < 2048) bias[i] = bih[i] + bhh[i];
}
__global__ void pack_conv1(const float* Wih, const float* Whh, const float* bih,
                           const float* bhh, __half* w1, float* bias)
{
    const int i = blockIdx.x * 256 + threadIdx.x;
    if (i < 2048 * 1024) {
        const int r = i >> 10, k = i & 1023;
        const float v = (k < 512) ? Wih[(size_t)r * 512 + k] : Whh[(size_t)r * 512 + (k - 512)];
        w1[i] = __float2half_rn(v);
    }
    if (i < 2048) bias[i] = bih[i] + bhh[i];
}
__global__ void split2_arr(const float* s, __half* t1, __half* t2, int n)
{ const int i = blockIdx.x * 256 + threadIdx.x; if (i < n) split2h(s[i], t1, t2, i); }
__global__ void conv1_arr(const float* s, __half* t1, int n)
{ const int i = blockIdx.x * 256 + threadIdx.x; if (i < n) t1[i] = __float2half_rn(s[i]); }
__global__ void transpose_t2h(const float* W, float* WT)
{
    const int i = blockIdx.x * 256 + threadIdx.x;
    if (i >= D_ * H_) return;
    const int d = i / H_, h = i - d * H_;
    WT[i] = W[(size_t)h * D_ + d];
}
__global__ void zero_state(__half* i1, __half* i2, __half* h1, __half* h2,
                           __half* q1, float* c2)
{
    const int i = blockIdx.x * 256 + threadIdx.x;
    if (i >= B_ * H_) return;
    const __half z = __float2half_rn(0.f);
    i1[i] = z; i2[i] = z; h1[i] = z; h2[i] = z; q1[i] = z; c2[i] = 0.f;
}

// ---------------- host ----------------
#define SYM(p, s) cudaGetSymbolAddress((void**)&p, s)

extern "C" void kernel_launch(void* const* d_in, const int* in_sizes, int n_in,
                              void* d_out, int out_size)
{
    const float* x = (const float*)d_in[0];
    const float* gumbel = (const float*)d_in[1];
    const float* in_W = (const float*)d_in[2];
    const float* in_b = (const float*)d_in[3];
    const float* out_W = (const float*)d_in[4];
    const float* out_b = (const float*)d_in[5];
    const float* eWih = (const float*)d_in[6];
    const float* eWhh = (const float*)d_in[7];
    const float* ebih = (const float*)d_in[8];
    const float* ebhh = (const float*)d_in[9];
    const float* dWih = (const float*)d_in[10];
    const float* dWhh = (const float*)d_in[11];
    const float* dbih = (const float*)d_in[12];
    const float* dbhh = (const float*)d_in[13];
    const float* h2t_W = (const float*)d_in[14];
    const float* h2t_b = (const float*)d_in[15];
    const float* t2h_W = (const float*)d_in[16];
    const float* t2h_b = (const float*)d_in[17];

    float* out = (float*)d_out;
    float* o_recon = out;
    float* o_oh = out + (size_t)B_ * O_;
    float* o_lg = o_oh + (size_t)B_ * L_ * D_;
    float* o_msg = o_lg + (size_t)B_ * L_ * D_;

    float *be, *bd, *t2hT, *cx, *cx2, *gates;
    __half *We1, *We2, *Wd1, *h2t1, *h2t2, *inW1, *inW2, *outW1;
    __half *x1, *x2, *inp1, *inp2, *hxA, *hxB, *hx21, *z1;
    SYM(be, g_be); SYM(bd, g_bd); SYM(t2hT, g_t2hT); SYM(cx, g_cx);
    SYM(cx2, g_cx2); SYM(gates, g_gates);
    SYM(We1, g_We1); SYM(We2, g_We2); SYM(Wd1, g_Wd1);
    SYM(h2t1, g_h2t1); SYM(h2t2, g_h2t2);
    SYM(inW1, g_inW1); SYM(inW2, g_inW2); SYM(outW1, g_outW1);
    SYM(x1, g_x1); SYM(x2, g_x2); SYM(inp1, g_inp1); SYM(inp2, g_inp2);
    SYM(hxA, g_hxA); SYM(hxB, g_hxB); SYM(hx21, g_hx21); SYM(z1, g_z1);

    const int S2 = 2 * 2 * (20480 + 10240);   // NS=2: 122880
    const int S1 = 2 * 1 * (20480 + 10240);   // NS=1: 61440
    cudaFuncSetAttribute(gemm_sp<2>, cudaFuncAttributeMaxDynamicSharedMemorySize, S2);
    cudaFuncSetAttribute(gemm_sp<1>, cudaFuncAttributeMaxDynamicSharedMemorySize, S1);

    // prep
    pack_split2<<<8192, 256>>>(eWih, eWhh, ebih, ebhh, We1, We2, be);
    pack_conv1<<<8192, 256>>>(dWih, dWhh, dbih, dbhh, Wd1, bd);
    transpose_t2h<<<(D_ * H_ + 255) / 256, 256>>>(t2h_W, t2hT);
    split2_arr<<<2048, 256>>>(h2t_W, h2t1, h2t2, D_ * H_);
    split2_arr<<<1024, 256>>>(in_W, inW1, inW2, H_ * 512);
    conv1_arr<<<1024, 256>>>(out_W, outW1, O_ * H_);
    split2_arr<<<4096, 256>>>(x, x1, x2, B_ * 512);
    zero_state<<<4096, 256>>>(inp1, inp2, hxA, hxB, hx21, cx2);

    // cx = x @ in_W^T + in_b  (exact 4-pair fp16)
    gemm_sp<2><<<dim3(4, 8), 256, S2>>>(x1, x2, x1, x2, inW1, inW2, in_b, cx,
                                        512, 512, 16, 16);

    // ---- encoder ----
    for (int t = 0; t < L_; t++) {
        gemm_sp<2><<<dim3(16, 8), 256, S2>>>(inp1, inp2, hxA, hxB, We1, We2, be,
                                             gates, 1024, 2048, 16, 32);
        lstm_pw2s<<<4096, 256>>>(gates, cx, hxA, hxB);
        gemm_sp<2><<<dim3(8, 8), 256, S2>>>(hxA, hxB, hxA, hxB, h2t1, h2t2, h2t_b,
                                            o_lg + (size_t)t * D_, 512, L_ * D_, 16, 16);
        softmax_st<<<B_, 256>>>(o_lg, gumbel, t, o_oh, o_msg, t2hT, t2h_b,
                                inp1, inp2, z1);
    }

    // ---- decoder ----
    for (int t = 0; t < L_; t++) {
        gemm_sp<1><<<dim3(16, 8), 256, S1>>>(z1 + (size_t)t * B_ * H_, nullptr,
                                             hx21, nullptr, Wd1, nullptr, bd,
                                             gates, 1024, 2048, 16, 32);
        lstm_pw1s<<<4096, 256>>>(gates, cx2, hx21);
    }
    gemm_sp<1><<<dim3(4, 8), 256, S1>>>(hx21, nullptr, hx21, nullptr, outW1, nullptr,
                                        out_b, o_recon, 512, 512, 16, 16);
}